// round 15
// baseline (speedup 1.0000x reference)
#include <cuda_runtime.h>
#include <cuda_fp16.h>
#include <cstdint>

#define N_DIM   16384
#define F_DIM   32
#define BM      128
#define SK      64                         // k floats per stage (256B per row)
#define THREADS 256
#define GRID    148
#define UNIT_STAGES 32
#define TOTAL_UNITS 1024                   // 128 m-tiles x 8 k-chunks

// ---- per-warp smem stage layout ----
#define WA_SZ    4096                      // 16 rows x 256B (swizzled)
#define ROWB     144                       // B fp16 row stride (128B + 16 pad)
#define WB_OFF   WA_SZ
#define WB_SZ    (32 * ROWB)               // 4608
#define WSTAGE   (WA_SZ + WB_SZ)           // 8704
#define NSTAGE   3
#define WARP_SMEM (NSTAGE * WSTAGE)        // 26112
#define SMEM_TOTAL (8 * WARP_SMEM)         // 208896 (1 CTA/SM)

__device__ __align__(16) __half g_b1[F_DIM * N_DIM];
__device__ __align__(16) __half g_b2[F_DIM * N_DIM];
// per-CTA flush slots: [cta][0..1][128 rows][32 cols] f32
__device__ __align__(16) float g_part[GRID * 2 * BM * F_DIM];

// ---------------- helpers ----------------
__device__ __forceinline__ uint32_t smem_u32(const void* p) {
    uint32_t a;
    asm("{ .reg .u64 t; cvta.to.shared.u64 t, %1; cvt.u32.u64 %0, t; }" : "=r"(a) : "l"(p));
    return a;
}
#define CP_ASYNC16_PF(dst, src) \
    asm volatile("cp.async.cg.shared.global.L2::256B [%0], [%1], 16;" :: "r"(dst), "l"(src) : "memory")
#define CP_ASYNC16(dst, src) \
    asm volatile("cp.async.cg.shared.global [%0], [%1], 16;" :: "r"(dst), "l"(src) : "memory")
#define CP_COMMIT()  asm volatile("cp.async.commit_group;" ::: "memory")
#define CP_WAIT1()   asm volatile("cp.async.wait_group 1;" ::: "memory")

__device__ __forceinline__ float2 lds_f2(uint32_t a) {
    float2 v;
    asm volatile("ld.shared.v2.f32 {%0,%1}, [%2];" : "=f"(v.x), "=f"(v.y) : "r"(a));
    return v;
}
__device__ __forceinline__ uint32_t lds32(uint32_t addr) {
    uint32_t v;
    asm volatile("ld.shared.b32 %0, [%1];" : "=r"(v) : "r"(addr));
    return v;
}
__device__ __forceinline__ void mma_f16(float* c, const uint32_t* a, uint32_t b0, uint32_t b1) {
    asm volatile("mma.sync.aligned.m16n8k16.row.col.f32.f16.f16.f32 "
                 "{%0,%1,%2,%3}, {%4,%5,%6,%7}, {%8,%9}, {%0,%1,%2,%3};"
                 : "+f"(c[0]), "+f"(c[1]), "+f"(c[2]), "+f"(c[3])
                 : "r"(a[0]), "r"(a[1]), "r"(a[2]), "r"(a[3]), "r"(b0), "r"(b1));
}
__device__ __forceinline__ uint32_t split2h(float2 v, uint32_t& lo) {
    __half2 h2 = __floats2half2_rn(v.x, v.y);
    float2 hf = __half22float2(h2);
    __half2 l2 = __floats2half2_rn(v.x - hf.x, v.y - hf.y);
    lo = *reinterpret_cast<uint32_t*>(&l2);
    return *reinterpret_cast<uint32_t*>(&h2);
}

// unit ownership math: u0(b) = floor(b*1024/148) = floor(b*256/37)
__device__ __forceinline__ int unit_start(int b) { return (b << 8) / 37; }
__device__ __forceinline__ int cta_of_unit(int u) { return (37 * u + 36) >> 8; }

// slot-sum for rows of m-tile m (8 units per m-tile)
__device__ __forceinline__ float4 sum_slots(int m, int lr, int c4) {
    const int bf = cta_of_unit(8 * m);
    const int bl = cta_of_unit(8 * m + 7);
    float4 acc = make_float4(0.f, 0.f, 0.f, 0.f);
    for (int b = bf; b <= bl; b++) {
        const int idx = m - (unit_start(b) >> 3);
        const float4 v = *reinterpret_cast<const float4*>(
            g_part + (((size_t)(b * 2 + idx)) << 12) + lr * F_DIM + c4);
        acc.x += v.x; acc.y += v.y; acc.z += v.z; acc.w += v.w;
    }
    return acc;
}

// ---------- prep: fp16((features @ W)^T) -> g_b1 ----------
__global__ void feat_w_kernel(const float* __restrict__ feat,
                              const float* __restrict__ W) {
    __shared__ float sW[F_DIM * F_DIM];
    int tid = threadIdx.x;
    for (int i = tid; i < F_DIM * F_DIM; i += 128) sW[i] = W[i];
    __syncthreads();
    int g = blockIdx.x * 128 + tid;
    int row = g >> 1;
    int c0  = (g & 1) * 16;
    float f[F_DIM];
    const float4* fr = reinterpret_cast<const float4*>(feat + (size_t)row * F_DIM);
#pragma unroll
    for (int i = 0; i < 8; i++) {
        float4 v = fr[i];
        f[4*i] = v.x; f[4*i+1] = v.y; f[4*i+2] = v.z; f[4*i+3] = v.w;
    }
#pragma unroll 4
    for (int cc = 0; cc < 16; cc++) {
        int c = c0 + cc;
        float acc = 0.f;
#pragma unroll
        for (int k = 0; k < F_DIM; k++) acc = fmaf(f[k], sW[k * F_DIM + c], acc);
        g_b1[(size_t)c * N_DIM + row] = __float2half_rn(acc);
    }
}

// ---------- persistent big GEMM: per-warp pipelines, 256B row bursts ----------
template <int MODE>
__global__ __launch_bounds__(THREADS, 1)
void big_gemm_mma(const float* __restrict__ A) {
    const __half* __restrict__ B = (MODE == 1) ? g_b1 : g_b2;

    extern __shared__ char smem[];
    const int tid  = threadIdx.x;
    const int lane = tid & 31;
    const int w    = tid >> 5;              // warp w -> rows w*16 .. w*16+15
    const uint32_t wb = smem_u32(smem) + (uint32_t)(w * WARP_SMEM);

    const int u0 = unit_start(blockIdx.x);
    const int u1 = unit_start(blockIdx.x + 1);
    const int S0 = u0 * UNIT_STAGES;
    const int S1 = u1 * UNIT_STAGES;

    // ---- producer slots (warp-local) ----
    // A: 16 rows x 16 granules(16B) = 256 chunks -> 8/lane
    int alr[8]; int agr[8]; uint32_t adst[8];
#pragma unroll
    for (int i = 0; i < 8; i++) {
        int chunk = lane + 32 * i;
        alr[i] = chunk >> 4;  agr[i] = chunk & 15;
        adst[i] = (uint32_t)(alr[i] * 256 + ((agr[i] ^ (alr[i] & 7)) << 4));
    }
    // B: 32 rows x 8 granules(16B) = 256 chunks -> 8/lane
    int bn[8]; int bgr[8]; uint32_t bdst[8];
#pragma unroll
    for (int j = 0; j < 8; j++) {
        int chunk = lane + 32 * j;
        bn[j] = chunk >> 3;  bgr[j] = chunk & 7;
        bdst[j] = (uint32_t)(WB_OFF + bn[j] * ROWB + bgr[j] * 16);
    }

    auto issue = [&](int s) {
        const int u = s >> 5;
        const int m = u >> 3;
        const int kf = ((u & 7) * UNIT_STAGES + (s & 31)) * SK;
        const uint32_t stg = wb + (uint32_t)(s % NSTAGE) * WSTAGE;
        const float* abase = A + (size_t)(m * BM + w * 16) * N_DIM + kf;
#pragma unroll
        for (int i = 0; i < 8; i++)
            CP_ASYNC16_PF(stg + adst[i], abase + (size_t)alr[i] * N_DIM + agr[i] * 4);
#pragma unroll
        for (int j = 0; j < 8; j++)
            CP_ASYNC16(stg + bdst[j], B + (size_t)bn[j] * N_DIM + kf + bgr[j] * 8);
    };

    // ---- consumer addressing (warp-local rows) ----
    const uint32_t xr  = (uint32_t)(lane >> 2);          // frag row 0..7
    const uint32_t ar0 = (uint32_t)((lane >> 2) * 256);
    const uint32_t gb  = (uint32_t)((lane & 3) >> 1);
    const uint32_t aib = (uint32_t)((lane & 1) * 8);
    const uint32_t boff = (uint32_t)(WB_OFF + (lane >> 2) * ROWB + (lane & 3) * 4);

    float acc[4][4];
#pragma unroll
    for (int j = 0; j < 4; j++)
#pragma unroll
        for (int i = 0; i < 4; i++) acc[j][i] = 0.f;

    issue(S0);     CP_COMMIT();
    issue(S0 + 1); CP_COMMIT();

    for (int s = S0; s < S1; s++) {
        CP_WAIT1();
        __syncwarp();
        if (s + 2 < S1) issue(s + 2);
        CP_COMMIT();   // unconditional: empty group keeps wait_group aligned

        const uint32_t stg = wb + (uint32_t)(s % NSTAGE) * WSTAGE;
#pragma unroll
        for (int kk = 0; kk < 4; kk++) {
            const uint32_t g0 = (uint32_t)(kk * 4 + gb) ^ xr;
            const uint32_t g2 = (uint32_t)(kk * 4 + gb + 2) ^ xr;
            uint32_t ah[4], al[4];
            {
                const uint32_t r0b = stg + ar0;
                float2 v0 = lds_f2(r0b + (g0 << 4) + aib);
                float2 v1 = lds_f2(r0b + 8 * 256 + (g0 << 4) + aib);
                float2 v2 = lds_f2(r0b + (g2 << 4) + aib);
                float2 v3 = lds_f2(r0b + 8 * 256 + (g2 << 4) + aib);
                ah[0] = split2h(v0, al[0]);
                ah[1] = split2h(v1, al[1]);
                ah[2] = split2h(v2, al[2]);
                ah[3] = split2h(v3, al[3]);
            }
            const uint32_t bH = stg + boff + (uint32_t)(kk * 32);
#pragma unroll
            for (int j = 0; j < 4; j++) {
                const uint32_t bo = bH + (uint32_t)(j * 8 * ROWB);
                uint32_t b0 = lds32(bo);
                uint32_t b1 = lds32(bo + 16);
                mma_f16(acc[j], ah, b0, b1);
                mma_f16(acc[j], al, b0, b1);
            }
        }

        // flush at m-tile boundary (256 stages) or range end
        if (((s + 1) & 255) == 0 || s + 1 == S1) {
            const int idx = (s >> 8) - (S0 >> 8);          // 0 or 1
            float* pp = g_part + (((size_t)(blockIdx.x * 2 + idx)) << 12);
            const int lr0 = w * 16 + (lane >> 2);
            const int lr1 = lr0 + 8;
#pragma unroll
            for (int j = 0; j < 4; j++) {
                const int c = j * 8 + (lane & 3) * 2;
                *reinterpret_cast<float2*>(pp + (size_t)lr0 * F_DIM + c) =
                    make_float2(acc[j][0], acc[j][1]);
                *reinterpret_cast<float2*>(pp + (size_t)lr1 * F_DIM + c) =
                    make_float2(acc[j][2], acc[j][3]);
                acc[j][0] = acc[j][1] = acc[j][2] = acc[j][3] = 0.f;
            }
        }
    }
}

// ---------- reduce slots -> diag scale -> fp16 -> g_b2 (transposed) ----------
__global__ void reduce_split_kernel(const float* __restrict__ diag) {
    __shared__ unsigned short sh[F_DIM][33];
    const int tid = threadIdx.x;
    const int r0 = blockIdx.x * 32;
    const int m  = r0 >> 7;                 // BM = 128
    const int rl = tid >> 3;
    const int c4 = (tid & 7) * 4;
    const int lr = (r0 & 127) + rl;
    float4 acc = sum_slots(m, lr, c4);
    const float d = diag[r0 + rl];
    float vv[4] = {acc.x * d, acc.y * d, acc.z * d, acc.w * d};
#pragma unroll
    for (int i = 0; i < 4; i++) {
        __half h = __float2half_rn(vv[i]);
        sh[c4 + i][rl] = *reinterpret_cast<unsigned short*>(&h);
    }
    __syncthreads();
    const int cc = tid >> 3;
    const int rr = (tid & 7) * 4;
    ushort4 oh = make_ushort4(sh[cc][rr], sh[cc][rr+1], sh[cc][rr+2], sh[cc][rr+3]);
    *reinterpret_cast<ushort4*>(&g_b2[(size_t)cc * N_DIM + r0 + rr]) = oh;
}

// ---------- reduce slots -> f32 out ----------
__global__ void reduce_out_kernel(float* __restrict__ out) {
    const int tid = threadIdx.x;
    const int r0 = blockIdx.x * 32;
    const int m  = r0 >> 7;
    const int rl = tid >> 3;
    const int c4 = (tid & 7) * 4;
    const int lr = (r0 & 127) + rl;
    float4 acc = sum_slots(m, lr, c4);
    *reinterpret_cast<float4*>(out + (size_t)(r0 + rl) * F_DIM + c4) = acc;
}

extern "C" void kernel_launch(void* const* d_in, const int* in_sizes, int n_in,
                              void* d_out, int out_size) {
    const float* feat = (const float*)d_in[0];  // [16384, 32]
    const float* wav  = (const float*)d_in[1];  // [16384, 16384]
    const float* wavi = (const float*)d_in[2];  // [16384, 16384]
    const float* diag = (const float*)d_in[3];  // [16384]
    const float* Wm   = (const float*)d_in[4];  // [32, 32]
    float* out = (float*)d_out;

    cudaFuncSetAttribute(big_gemm_mma<1>, cudaFuncAttributeMaxDynamicSharedMemorySize, SMEM_TOTAL);
    cudaFuncSetAttribute(big_gemm_mma<2>, cudaFuncAttributeMaxDynamicSharedMemorySize, SMEM_TOTAL);

    feat_w_kernel<<<N_DIM * 2 / 128, 128>>>(feat, Wm);
    big_gemm_mma<1><<<GRID, THREADS, SMEM_TOTAL>>>(wavi);
    reduce_split_kernel<<<N_DIM / 32, 256>>>(diag);
    big_gemm_mma<2><<<GRID, THREADS, SMEM_TOTAL>>>(wav);
    reduce_out_kernel<<<N_DIM / 32, 256>>>(out);
}

// round 16
// speedup vs baseline: 1.0305x; 1.0305x over previous
#include <cuda_runtime.h>
#include <cuda_fp16.h>
#include <cstdint>

#define N_DIM   16384
#define F_DIM   32
#define BM      256
#define BK      32
#define THREADS 256
#define GRID    148
#define UNIT_STAGES 32
#define TOTAL_STAGES 32768                 // 64 m-tiles x 512 stages

// ---- per-warp smem stage layout (r14-proven) ----
#define WA_SZ    4096                      // 32 rows x 128B (swizzled)
#define ROWB     80
#define WB_OFF   WA_SZ
#define WB_SZ    (32 * ROWB)               // 2560
#define WSTAGE   (WA_SZ + WB_SZ)           // 6656
#define NSTAGE   4
#define WARP_SMEM (NSTAGE * WSTAGE)        // 26624
#define SMEM_TOTAL (8 * WARP_SMEM)         // 212992 (1 CTA/SM)

__device__ __align__(16) __half g_b1[F_DIM * N_DIM];
__device__ __align__(16) __half g_b2[F_DIM * N_DIM];
// per-CTA flush slots: [cta][0..1][256 rows][32 cols] f32
__device__ __align__(16) float g_part[GRID * 2 * BM * F_DIM];

// ---------------- helpers ----------------
__device__ __forceinline__ uint32_t smem_u32(const void* p) {
    uint32_t a;
    asm("{ .reg .u64 t; cvta.to.shared.u64 t, %1; cvt.u32.u64 %0, t; }" : "=r"(a) : "l"(p));
    return a;
}
#define CP_ASYNC16_PF(dst, src) \
    asm volatile("cp.async.cg.shared.global.L2::256B [%0], [%1], 16;" :: "r"(dst), "l"(src) : "memory")
#define CP_COMMIT()  asm volatile("cp.async.commit_group;" ::: "memory")
#define CP_WAIT2()   asm volatile("cp.async.wait_group 2;" ::: "memory")

__device__ __forceinline__ float2 lds_f2(uint32_t a) {
    float2 v;
    asm volatile("ld.shared.v2.f32 {%0,%1}, [%2];" : "=f"(v.x), "=f"(v.y) : "r"(a));
    return v;
}
__device__ __forceinline__ uint32_t lds32(uint32_t addr) {
    uint32_t v;
    asm volatile("ld.shared.b32 %0, [%1];" : "=r"(v) : "r"(addr));
    return v;
}
__device__ __forceinline__ void mma_f16(float* c, const uint32_t* a, uint32_t b0, uint32_t b1) {
    asm volatile("mma.sync.aligned.m16n8k16.row.col.f32.f16.f16.f32 "
                 "{%0,%1,%2,%3}, {%4,%5,%6,%7}, {%8,%9}, {%0,%1,%2,%3};"
                 : "+f"(c[0]), "+f"(c[1]), "+f"(c[2]), "+f"(c[3])
                 : "r"(a[0]), "r"(a[1]), "r"(a[2]), "r"(a[3]), "r"(b0), "r"(b1));
}
__device__ __forceinline__ uint32_t split2h(float2 v, uint32_t& lo) {
    __half2 h2 = __floats2half2_rn(v.x, v.y);
    float2 hf = __half22float2(h2);
    __half2 l2 = __floats2half2_rn(v.x - hf.x, v.y - hf.y);
    lo = *reinterpret_cast<uint32_t*>(&l2);
    return *reinterpret_cast<uint32_t*>(&h2);
}

// ---- stage-granular work split: S0(b) = b*32768/148 = b*8192/37 ----
__device__ __forceinline__ int stage_start(int b) { return (b * 8192) / 37; }
// largest b with stage_start(b) <= s
__device__ __forceinline__ int cta_of_stage(int s) { return (37 * s + 36) >> 13; }

// slot-sum over all CTAs whose ranges intersect m-tile m (stages [512m, 512m+512))
__device__ __forceinline__ float4 sum_slots(int m, int lr, int c4) {
    const int bf = cta_of_stage(512 * m);
    const int bl = cta_of_stage(512 * m + 511);
    float4 acc = make_float4(0.f, 0.f, 0.f, 0.f);
    for (int b = bf; b <= bl; b++) {
        const int idx = m - (stage_start(b) >> 9);
        const float4 v = *reinterpret_cast<const float4*>(
            g_part + (((size_t)(b * 2 + idx)) << 13) + lr * F_DIM + c4);
        acc.x += v.x; acc.y += v.y; acc.z += v.z; acc.w += v.w;
    }
    return acc;
}

// ---------- prep: fp16((features @ W)^T) -> g_b1 (4 threads per row) ----------
__global__ void feat_w_kernel(const float* __restrict__ feat,
                              const float* __restrict__ W) {
    __shared__ float sW[F_DIM * F_DIM];
    int tid = threadIdx.x;
    for (int i = tid; i < F_DIM * F_DIM; i += 128) sW[i] = W[i];
    __syncthreads();
    int g = blockIdx.x * 128 + tid;
    int row = g >> 2;
    int c0  = (g & 3) * 8;
    float f[F_DIM];
    const float4* fr = reinterpret_cast<const float4*>(feat + (size_t)row * F_DIM);
#pragma unroll
    for (int i = 0; i < 8; i++) {
        float4 v = fr[i];
        f[4*i] = v.x; f[4*i+1] = v.y; f[4*i+2] = v.z; f[4*i+3] = v.w;
    }
#pragma unroll
    for (int cc = 0; cc < 8; cc++) {
        int c = c0 + cc;
        float acc = 0.f;
#pragma unroll
        for (int k = 0; k < F_DIM; k++) acc = fmaf(f[k], sW[k * F_DIM + c], acc);
        g_b1[(size_t)c * N_DIM + row] = __float2half_rn(acc);
    }
}

// ---------- persistent big GEMM: per-warp pipelines, stage-granular split ----------
template <int MODE>
__global__ __launch_bounds__(THREADS, 1)
void big_gemm_mma(const float* __restrict__ A) {
    const __half* __restrict__ B = (MODE == 1) ? g_b1 : g_b2;

    extern __shared__ char smem[];
    const int tid  = threadIdx.x;
    const int lane = tid & 31;
    const int w    = tid >> 5;
    const uint32_t wb = smem_u32(smem) + (uint32_t)(w * WARP_SMEM);

    const int S0 = stage_start(blockIdx.x);
    const int S1 = stage_start(blockIdx.x + 1);

    // ---- producer slots (warp-local) ----
    int alr[8]; int agr[8]; uint32_t adst[8];
#pragma unroll
    for (int i = 0; i < 8; i++) {
        int chunk = lane + 32 * i;
        alr[i] = chunk >> 3;  agr[i] = chunk & 7;
        adst[i] = (uint32_t)(alr[i] * 128 + ((agr[i] ^ (alr[i] & 7)) << 4));
    }
    int bn[4]; int bgr[4]; uint32_t bdst[4];
#pragma unroll
    for (int j = 0; j < 4; j++) {
        int chunk = lane + 32 * j;
        bn[j] = chunk >> 2;  bgr[j] = chunk & 3;
        bdst[j] = (uint32_t)(WB_OFF + bn[j] * ROWB + bgr[j] * 16);
    }

    auto issue = [&](int s) {
        const int u = s >> 5;
        const int m = u >> 4;
        const int kf = ((u & 15) * UNIT_STAGES + (s & 31)) * BK;
        const uint32_t stg = wb + (uint32_t)(s & 3) * WSTAGE;
        const float* abase = A + (size_t)(m * BM + w * 32) * N_DIM + kf;
#pragma unroll
        for (int i = 0; i < 8; i++)
            CP_ASYNC16_PF(stg + adst[i], abase + (size_t)alr[i] * N_DIM + agr[i] * 4);
#pragma unroll
        for (int j = 0; j < 4; j++)
            CP_ASYNC16_PF(stg + bdst[j], B + (size_t)bn[j] * N_DIM + kf + bgr[j] * 8);
    };

    // ---- consumer addressing (warp-local rows) ----
    const uint32_t xr  = (uint32_t)(lane >> 2);
    const uint32_t ar0 = (uint32_t)((lane >> 2) * 128);
    const uint32_t gb  = (uint32_t)((lane & 3) >> 1);
    const uint32_t aib = (uint32_t)((lane & 1) * 8);
    const uint32_t boff = (uint32_t)(WB_OFF + (lane >> 2) * ROWB + (lane & 3) * 4);

    float acc[2][4][4];
#pragma unroll
    for (int t = 0; t < 2; t++)
#pragma unroll
        for (int j = 0; j < 4; j++)
#pragma unroll
            for (int i = 0; i < 4; i++) acc[t][j][i] = 0.f;

    issue(S0);     CP_COMMIT();
    issue(S0 + 1); CP_COMMIT();
    issue(S0 + 2); CP_COMMIT();

    for (int s = S0; s < S1; s++) {
        CP_WAIT2();
        __syncwarp();
        if (s + 3 < S1) issue(s + 3);
        CP_COMMIT();   // unconditional: empty group keeps wait_group aligned

        const uint32_t stg = wb + (uint32_t)(s & 3) * WSTAGE;
#pragma unroll
        for (int kk = 0; kk < 2; kk++) {
            const uint32_t g0 = (gb + (uint32_t)(kk * 4)) ^ xr;
            const uint32_t g2 = (gb + (uint32_t)(kk * 4) + 2) ^ xr;
            uint32_t ah[2][4], al[2][4];
#pragma unroll
            for (int t = 0; t < 2; t++) {
                const uint32_t r0b = stg + ar0 + (uint32_t)(t * 16 * 128);
                float2 v0 = lds_f2(r0b + (g0 << 4) + aib);
                float2 v1 = lds_f2(r0b + 8 * 128 + (g0 << 4) + aib);
                float2 v2 = lds_f2(r0b + (g2 << 4) + aib);
                float2 v3 = lds_f2(r0b + 8 * 128 + (g2 << 4) + aib);
                ah[t][0] = split2h(v0, al[t][0]);
                ah[t][1] = split2h(v1, al[t][1]);
                ah[t][2] = split2h(v2, al[t][2]);
                ah[t][3] = split2h(v3, al[t][3]);
            }
            const uint32_t bH = stg + boff + (uint32_t)(kk * 32);
#pragma unroll
            for (int j = 0; j < 4; j++) {
                const uint32_t bo = bH + (uint32_t)(j * 8 * ROWB);
                uint32_t b0 = lds32(bo);
                uint32_t b1 = lds32(bo + 16);
#pragma unroll
                for (int t = 0; t < 2; t++) {
                    mma_f16(acc[t][j], ah[t], b0, b1);
                    mma_f16(acc[t][j], al[t], b0, b1);
                }
            }
        }

        // flush at m-tile boundary (512 stages) or range end
        if (((s + 1) & 511) == 0 || s + 1 == S1) {
            const int idx = (s >> 9) - (S0 >> 9);          // 0 or 1
            float* pp = g_part + (((size_t)(blockIdx.x * 2 + idx)) << 13);
#pragma unroll
            for (int t = 0; t < 2; t++) {
                const int lr0 = w * 32 + t * 16 + (lane >> 2);
                const int lr1 = lr0 + 8;
#pragma unroll
                for (int j = 0; j < 4; j++) {
                    const int c = j * 8 + (lane & 3) * 2;
                    *reinterpret_cast<float2*>(pp + (size_t)lr0 * F_DIM + c) =
                        make_float2(acc[t][j][0], acc[t][j][1]);
                    *reinterpret_cast<float2*>(pp + (size_t)lr1 * F_DIM + c) =
                        make_float2(acc[t][j][2], acc[t][j][3]);
                    acc[t][j][0] = acc[t][j][1] = acc[t][j][2] = acc[t][j][3] = 0.f;
                }
            }
        }
    }
}

// ---------- reduce slots -> diag scale -> fp16 -> g_b2 (transposed) ----------
__global__ void reduce_split_kernel(const float* __restrict__ diag) {
    __shared__ unsigned short sh[F_DIM][33];
    const int tid = threadIdx.x;
    const int r0 = blockIdx.x * 32;
    const int m  = r0 >> 8;
    const int rl = tid >> 3;
    const int c4 = (tid & 7) * 4;
    const int lr = (r0 & 255) + rl;
    float4 acc = sum_slots(m, lr, c4);
    const float d = diag[r0 + rl];
    float vv[4] = {acc.x * d, acc.y * d, acc.z * d, acc.w * d};
#pragma unroll
    for (int i = 0; i < 4; i++) {
        __half h = __float2half_rn(vv[i]);
        sh[c4 + i][rl] = *reinterpret_cast<unsigned short*>(&h);
    }
    __syncthreads();
    const int cc = tid >> 3;
    const int rr = (tid & 7) * 4;
    ushort4 oh = make_ushort4(sh[cc][rr], sh[cc][rr+1], sh[cc][rr+2], sh[cc][rr+3]);
    *reinterpret_cast<ushort4*>(&g_b2[(size_t)cc * N_DIM + r0 + rr]) = oh;
}

// ---------- reduce slots -> f32 out ----------
__global__ void reduce_out_kernel(float* __restrict__ out) {
    const int tid = threadIdx.x;
    const int r0 = blockIdx.x * 32;
    const int m  = r0 >> 8;
    const int rl = tid >> 3;
    const int c4 = (tid & 7) * 4;
    const int lr = (r0 & 255) + rl;
    float4 acc = sum_slots(m, lr, c4);
    *reinterpret_cast<float4*>(out + (size_t)(r0 + rl) * F_DIM + c4) = acc;
}

extern "C" void kernel_launch(void* const* d_in, const int* in_sizes, int n_in,
                              void* d_out, int out_size) {
    const float* feat = (const float*)d_in[0];  // [16384, 32]
    const float* wav  = (const float*)d_in[1];  // [16384, 16384]
    const float* wavi = (const float*)d_in[2];  // [16384, 16384]
    const float* diag = (const float*)d_in[3];  // [16384]
    const float* Wm   = (const float*)d_in[4];  // [32, 32]
    float* out = (float*)d_out;

    cudaFuncSetAttribute(big_gemm_mma<1>, cudaFuncAttributeMaxDynamicSharedMemorySize, SMEM_TOTAL);
    cudaFuncSetAttribute(big_gemm_mma<2>, cudaFuncAttributeMaxDynamicSharedMemorySize, SMEM_TOTAL);

    feat_w_kernel<<<N_DIM * 4 / 128, 128>>>(feat, Wm);
    big_gemm_mma<1><<<GRID, THREADS, SMEM_TOTAL>>>(wavi);
    reduce_split_kernel<<<N_DIM / 32, 256>>>(diag);
    big_gemm_mma<2><<<GRID, THREADS, SMEM_TOTAL>>>(wav);
    reduce_out_kernel<<<N_DIM / 32, 256>>>(out);
}

// round 17
// speedup vs baseline: 1.0362x; 1.0056x over previous
#include <cuda_runtime.h>
#include <cuda_fp16.h>
#include <cstdint>

#define N_DIM   16384
#define F_DIM   32
#define BM      256
#define BK      32
#define THREADS 256
#define GRID    152                        // GB300: 152 SMs (B300_MICROARCH)
#define UNIT_STAGES 32
#define TOTAL_STAGES 32768                 // 64 m-tiles x 512 stages

// ---- per-warp smem stage layout (r14/r16-proven) ----
#define WA_SZ    4096                      // 32 rows x 128B (swizzled)
#define ROWB     80
#define WB_OFF   WA_SZ
#define WB_SZ    (32 * ROWB)               // 2560
#define WSTAGE   (WA_SZ + WB_SZ)           // 6656
#define NSTAGE   4
#define WARP_SMEM (NSTAGE * WSTAGE)        // 26624
#define SMEM_TOTAL (8 * WARP_SMEM)         // 212992 (1 CTA/SM)

__device__ __align__(16) __half g_b1[F_DIM * N_DIM];
__device__ __align__(16) __half g_b2[F_DIM * N_DIM];
// per-CTA flush slots: [cta][0..1][256 rows][32 cols] f32
__device__ __align__(16) float g_part[GRID * 2 * BM * F_DIM];

// ---------------- helpers ----------------
__device__ __forceinline__ uint32_t smem_u32(const void* p) {
    uint32_t a;
    asm("{ .reg .u64 t; cvta.to.shared.u64 t, %1; cvt.u32.u64 %0, t; }" : "=r"(a) : "l"(p));
    return a;
}
#define CP_ASYNC16_PF(dst, src) \
    asm volatile("cp.async.cg.shared.global.L2::256B [%0], [%1], 16;" :: "r"(dst), "l"(src) : "memory")
#define CP_COMMIT()  asm volatile("cp.async.commit_group;" ::: "memory")
#define CP_WAIT2()   asm volatile("cp.async.wait_group 2;" ::: "memory")

__device__ __forceinline__ float2 lds_f2(uint32_t a) {
    float2 v;
    asm volatile("ld.shared.v2.f32 {%0,%1}, [%2];" : "=f"(v.x), "=f"(v.y) : "r"(a));
    return v;
}
__device__ __forceinline__ uint32_t lds32(uint32_t addr) {
    uint32_t v;
    asm volatile("ld.shared.b32 %0, [%1];" : "=r"(v) : "r"(addr));
    return v;
}
__device__ __forceinline__ void mma_f16(float* c, const uint32_t* a, uint32_t b0, uint32_t b1) {
    asm volatile("mma.sync.aligned.m16n8k16.row.col.f32.f16.f16.f32 "
                 "{%0,%1,%2,%3}, {%4,%5,%6,%7}, {%8,%9}, {%0,%1,%2,%3};"
                 : "+f"(c[0]), "+f"(c[1]), "+f"(c[2]), "+f"(c[3])
                 : "r"(a[0]), "r"(a[1]), "r"(a[2]), "r"(a[3]), "r"(b0), "r"(b1));
}
__device__ __forceinline__ uint32_t split2h(float2 v, uint32_t& lo) {
    __half2 h2 = __floats2half2_rn(v.x, v.y);
    float2 hf = __half22float2(h2);
    __half2 l2 = __floats2half2_rn(v.x - hf.x, v.y - hf.y);
    lo = *reinterpret_cast<uint32_t*>(&l2);
    return *reinterpret_cast<uint32_t*>(&h2);
}

// ---- stage-granular work split for GRID=152: S0(b) = b*32768/152 = b*4096/19 ----
__device__ __forceinline__ int stage_start(int b) { return (b << 12) / 19; }
// largest b with stage_start(b) <= s
__device__ __forceinline__ int cta_of_stage(int s) { return (19 * s + 18) >> 12; }

// slot-sum over all CTAs whose ranges intersect m-tile m (stages [512m, 512m+512))
__device__ __forceinline__ float4 sum_slots(int m, int lr, int c4) {
    const int bf = cta_of_stage(512 * m);
    const int bl = cta_of_stage(512 * m + 511);
    float4 acc = make_float4(0.f, 0.f, 0.f, 0.f);
    for (int b = bf; b <= bl; b++) {
        const int idx = m - (stage_start(b) >> 9);
        const float4 v = *reinterpret_cast<const float4*>(
            g_part + (((size_t)(b * 2 + idx)) << 13) + lr * F_DIM + c4);
        acc.x += v.x; acc.y += v.y; acc.z += v.z; acc.w += v.w;
    }
    return acc;
}

// ---------- prep: fp16((features @ W)^T) -> g_b1 (4 threads per row) ----------
__global__ void feat_w_kernel(const float* __restrict__ feat,
                              const float* __restrict__ W) {
    __shared__ float sW[F_DIM * F_DIM];
    int tid = threadIdx.x;
    for (int i = tid; i < F_DIM * F_DIM; i += 128) sW[i] = W[i];
    __syncthreads();
    int g = blockIdx.x * 128 + tid;
    int row = g >> 2;
    int c0  = (g & 3) * 8;
    float f[F_DIM];
    const float4* fr = reinterpret_cast<const float4*>(feat + (size_t)row * F_DIM);
#pragma unroll
    for (int i = 0; i < 8; i++) {
        float4 v = fr[i];
        f[4*i] = v.x; f[4*i+1] = v.y; f[4*i+2] = v.z; f[4*i+3] = v.w;
    }
#pragma unroll
    for (int cc = 0; cc < 8; cc++) {
        int c = c0 + cc;
        float acc = 0.f;
#pragma unroll
        for (int k = 0; k < F_DIM; k++) acc = fmaf(f[k], sW[k * F_DIM + c], acc);
        g_b1[(size_t)c * N_DIM + row] = __float2half_rn(acc);
    }
}

// ---------- persistent big GEMM: per-warp pipelines, stage-granular split ----------
template <int MODE>
__global__ __launch_bounds__(THREADS, 1)
void big_gemm_mma(const float* __restrict__ A) {
    const __half* __restrict__ B = (MODE == 1) ? g_b1 : g_b2;

    extern __shared__ char smem[];
    const int tid  = threadIdx.x;
    const int lane = tid & 31;
    const int w    = tid >> 5;
    const uint32_t wb = smem_u32(smem) + (uint32_t)(w * WARP_SMEM);

    const int S0 = stage_start(blockIdx.x);
    const int S1 = stage_start(blockIdx.x + 1);

    // ---- producer slots (warp-local) ----
    int alr[8]; int agr[8]; uint32_t adst[8];
#pragma unroll
    for (int i = 0; i < 8; i++) {
        int chunk = lane + 32 * i;
        alr[i] = chunk >> 3;  agr[i] = chunk & 7;
        adst[i] = (uint32_t)(alr[i] * 128 + ((agr[i] ^ (alr[i] & 7)) << 4));
    }
    int bn[4]; int bgr[4]; uint32_t bdst[4];
#pragma unroll
    for (int j = 0; j < 4; j++) {
        int chunk = lane + 32 * j;
        bn[j] = chunk >> 2;  bgr[j] = chunk & 3;
        bdst[j] = (uint32_t)(WB_OFF + bn[j] * ROWB + bgr[j] * 16);
    }

    auto issue = [&](int s) {
        const int u = s >> 5;
        const int m = u >> 4;
        const int kf = ((u & 15) * UNIT_STAGES + (s & 31)) * BK;
        const uint32_t stg = wb + (uint32_t)(s & 3) * WSTAGE;
        const float* abase = A + (size_t)(m * BM + w * 32) * N_DIM + kf;
#pragma unroll
        for (int i = 0; i < 8; i++)
            CP_ASYNC16_PF(stg + adst[i], abase + (size_t)alr[i] * N_DIM + agr[i] * 4);
#pragma unroll
        for (int j = 0; j < 4; j++)
            CP_ASYNC16_PF(stg + bdst[j], B + (size_t)bn[j] * N_DIM + kf + bgr[j] * 8);
    };

    // ---- consumer addressing (warp-local rows) ----
    const uint32_t xr  = (uint32_t)(lane >> 2);
    const uint32_t ar0 = (uint32_t)((lane >> 2) * 128);
    const uint32_t gb  = (uint32_t)((lane & 3) >> 1);
    const uint32_t aib = (uint32_t)((lane & 1) * 8);
    const uint32_t boff = (uint32_t)(WB_OFF + (lane >> 2) * ROWB + (lane & 3) * 4);

    float acc[2][4][4];
#pragma unroll
    for (int t = 0; t < 2; t++)
#pragma unroll
        for (int j = 0; j < 4; j++)
#pragma unroll
            for (int i = 0; i < 4; i++) acc[t][j][i] = 0.f;

    issue(S0);     CP_COMMIT();
    issue(S0 + 1); CP_COMMIT();
    issue(S0 + 2); CP_COMMIT();

    for (int s = S0; s < S1; s++) {
        CP_WAIT2();
        __syncwarp();
        if (s + 3 < S1) issue(s + 3);
        CP_COMMIT();   // unconditional: empty group keeps wait_group aligned

        const uint32_t stg = wb + (uint32_t)(s & 3) * WSTAGE;
#pragma unroll
        for (int kk = 0; kk < 2; kk++) {
            const uint32_t g0 = (gb + (uint32_t)(kk * 4)) ^ xr;
            const uint32_t g2 = (gb + (uint32_t)(kk * 4) + 2) ^ xr;
            uint32_t ah[2][4], al[2][4];
#pragma unroll
            for (int t = 0; t < 2; t++) {
                const uint32_t r0b = stg + ar0 + (uint32_t)(t * 16 * 128);
                float2 v0 = lds_f2(r0b + (g0 << 4) + aib);
                float2 v1 = lds_f2(r0b + 8 * 128 + (g0 << 4) + aib);
                float2 v2 = lds_f2(r0b + (g2 << 4) + aib);
                float2 v3 = lds_f2(r0b + 8 * 128 + (g2 << 4) + aib);
                ah[t][0] = split2h(v0, al[t][0]);
                ah[t][1] = split2h(v1, al[t][1]);
                ah[t][2] = split2h(v2, al[t][2]);
                ah[t][3] = split2h(v3, al[t][3]);
            }
            const uint32_t bH = stg + boff + (uint32_t)(kk * 32);
#pragma unroll
            for (int j = 0; j < 4; j++) {
                const uint32_t bo = bH + (uint32_t)(j * 8 * ROWB);
                uint32_t b0 = lds32(bo);
                uint32_t b1 = lds32(bo + 16);
#pragma unroll
                for (int t = 0; t < 2; t++) {
                    mma_f16(acc[t][j], ah[t], b0, b1);
                    mma_f16(acc[t][j], al[t], b0, b1);
                }
            }
        }

        // flush at m-tile boundary (512 stages) or range end
        if (((s + 1) & 511) == 0 || s + 1 == S1) {
            const int idx = (s >> 9) - (S0 >> 9);          // 0 or 1
            float* pp = g_part + (((size_t)(blockIdx.x * 2 + idx)) << 13);
#pragma unroll
            for (int t = 0; t < 2; t++) {
                const int lr0 = w * 32 + t * 16 + (lane >> 2);
                const int lr1 = lr0 + 8;
#pragma unroll
                for (int j = 0; j < 4; j++) {
                    const int c = j * 8 + (lane & 3) * 2;
                    *reinterpret_cast<float2*>(pp + (size_t)lr0 * F_DIM + c) =
                        make_float2(acc[t][j][0], acc[t][j][1]);
                    *reinterpret_cast<float2*>(pp + (size_t)lr1 * F_DIM + c) =
                        make_float2(acc[t][j][2], acc[t][j][3]);
                    acc[t][j][0] = acc[t][j][1] = acc[t][j][2] = acc[t][j][3] = 0.f;
                }
            }
        }
    }
}

// ---------- reduce slots -> diag scale -> fp16 -> g_b2 (transposed) ----------
__global__ void reduce_split_kernel(const float* __restrict__ diag) {
    __shared__ unsigned short sh[F_DIM][33];
    const int tid = threadIdx.x;
    const int r0 = blockIdx.x * 32;
    const int m  = r0 >> 8;
    const int rl = tid >> 3;
    const int c4 = (tid & 7) * 4;
    const int lr = (r0 & 255) + rl;
    float4 acc = sum_slots(m, lr, c4);
    const float d = diag[r0 + rl];
    float vv[4] = {acc.x * d, acc.y * d, acc.z * d, acc.w * d};
#pragma unroll
    for (int i = 0; i < 4; i++) {
        __half h = __float2half_rn(vv[i]);
        sh[c4 + i][rl] = *reinterpret_cast<unsigned short*>(&h);
    }
    __syncthreads();
    const int cc = tid >> 3;
    const int rr = (tid & 7) * 4;
    ushort4 oh = make_ushort4(sh[cc][rr], sh[cc][rr+1], sh[cc][rr+2], sh[cc][rr+3]);
    *reinterpret_cast<ushort4*>(&g_b2[(size_t)cc * N_DIM + r0 + rr]) = oh;
}

// ---------- reduce slots -> f32 out ----------
__global__ void reduce_out_kernel(float* __restrict__ out) {
    const int tid = threadIdx.x;
    const int r0 = blockIdx.x * 32;
    const int m  = r0 >> 8;
    const int rl = tid >> 3;
    const int c4 = (tid & 7) * 4;
    const int lr = (r0 & 255) + rl;
    float4 acc = sum_slots(m, lr, c4);
    *reinterpret_cast<float4*>(out + (size_t)(r0 + rl) * F_DIM + c4) = acc;
}

extern "C" void kernel_launch(void* const* d_in, const int* in_sizes, int n_in,
                              void* d_out, int out_size) {
    const float* feat = (const float*)d_in[0];  // [16384, 32]
    const float* wav  = (const float*)d_in[1];  // [16384, 16384]
    const float* wavi = (const float*)d_in[2];  // [16384, 16384]
    const float* diag = (const float*)d_in[3];  // [16384]
    const float* Wm   = (const float*)d_in[4];  // [32, 32]
    float* out = (float*)d_out;

    cudaFuncSetAttribute(big_gemm_mma<1>, cudaFuncAttributeMaxDynamicSharedMemorySize, SMEM_TOTAL);
    cudaFuncSetAttribute(big_gemm_mma<2>, cudaFuncAttributeMaxDynamicSharedMemorySize, SMEM_TOTAL);

    feat_w_kernel<<<N_DIM * 4 / 128, 128>>>(feat, Wm);
    big_gemm_mma<1><<<GRID, THREADS, SMEM_TOTAL>>>(wavi);
    reduce_split_kernel<<<N_DIM / 32, 256>>>(diag);
    big_gemm_mma<2><<<GRID, THREADS, SMEM_TOTAL>>>(wav);
    reduce_out_kernel<<<N_DIM / 32, 256>>>(out);
}